// round 1
// baseline (speedup 1.0000x reference)
#include <cuda_runtime.h>

#define N_CONS 10000
#define N_COLS 10000
#define NN     20000
#define NE     200000
#define NE2    (NE + NN)        // edges + self loops = 220000
#define NEG_SLOPE 0.2f

// ---------------- scratch (static __device__ globals; no allocs) ------------
__device__ float g_emb0[(size_t)NN * 128];
__device__ float g_xp1 [(size_t)NN * 1024];
__device__ float g_emb1[(size_t)NN * 1024];
__device__ float g_xp2 [(size_t)NN * 128];
__device__ float g_emb2[(size_t)NN * 128];
__device__ float g_asrc[(size_t)NN * 8];
__device__ float g_adst[(size_t)NN * 8];
__device__ float g_alpha[(size_t)NE2 * 8];
__device__ int   g_deg[NN];
__device__ int   g_rowptr[NN + 1];
__device__ int   g_wpos[NN];
__device__ int   g_csrc[NE2];
__device__ int   g_is64;

// ---------------- initial embedding ----------------------------------------
// emb0[n,k] = relu( tile(features,2) @ W.T + b )
__global__ void k_embed(const float* __restrict__ cs, const float* __restrict__ co,
                        const float* __restrict__ nW, const float* __restrict__ nb,
                        const float* __restrict__ cW, const float* __restrict__ cb)
{
    int idx = blockIdx.x * blockDim.x + threadIdx.x;
    if (idx >= NN * 128) return;
    int n = idx >> 7, k = idx & 127;
    float s;
    if (n < N_CONS) {
        s = nb[k];
        const float* x = cs + (size_t)n * 4;
        const float* w = nW + (size_t)k * 8;
#pragma unroll
        for (int j = 0; j < 8; j++) s += x[j & 3] * w[j];
    } else {
        int m = n - N_CONS;
        s = cb[k];
        const float* x = co + (size_t)m * 8;
        const float* w = cW + (size_t)k * 16;
#pragma unroll
        for (int j = 0; j < 16; j++) s += x[j & 7] * w[j];
    }
    g_emb0[idx] = fmaxf(s, 0.f);
}

// ---------------- tiled fp32 GEMM: C[M,N] = A[M,K] @ W[N,K]^T ---------------
template <bool RELU, bool BIAS>
__global__ void k_gemm(const float* __restrict__ A, const float* __restrict__ W,
                       const float* __restrict__ bias, float* __restrict__ C,
                       int M, int N, int K)
{
    __shared__ __align__(16) float As[16][68];
    __shared__ __align__(16) float Bs[16][68];
    int tid = threadIdx.x;
    int tx = tid & 15, ty = tid >> 4;
    int m0 = blockIdx.y * 64, n0 = blockIdx.x * 64;
    int lr = tid >> 2;          // tile row 0..63
    int lk = (tid & 3) * 4;     // k offset 0,4,8,12
    float acc[4][4] = {};

    for (int k0 = 0; k0 < K; k0 += 16) {
        int ar = m0 + lr;
        float4 av = (ar < M) ? *(const float4*)(A + (size_t)ar * K + k0 + lk)
                             : make_float4(0.f, 0.f, 0.f, 0.f);
        As[lk + 0][lr] = av.x; As[lk + 1][lr] = av.y;
        As[lk + 2][lr] = av.z; As[lk + 3][lr] = av.w;
        float4 bv = *(const float4*)(W + (size_t)(n0 + lr) * K + k0 + lk);
        Bs[lk + 0][lr] = bv.x; Bs[lk + 1][lr] = bv.y;
        Bs[lk + 2][lr] = bv.z; Bs[lk + 3][lr] = bv.w;
        __syncthreads();
#pragma unroll
        for (int k = 0; k < 16; k++) {
            float4 a = *(const float4*)&As[k][ty * 4];
            float4 b = *(const float4*)&Bs[k][tx * 4];
            float ar4[4] = {a.x, a.y, a.z, a.w};
            float br4[4] = {b.x, b.y, b.z, b.w};
#pragma unroll
            for (int i = 0; i < 4; i++)
#pragma unroll
                for (int j = 0; j < 4; j++) acc[i][j] += ar4[i] * br4[j];
        }
        __syncthreads();
    }
#pragma unroll
    for (int i = 0; i < 4; i++) {
        int m = m0 + ty * 4 + i;
        if (m >= M) continue;
#pragma unroll
        for (int j = 0; j < 4; j++) {
            int n = n0 + tx * 4 + j;
            float v = acc[i][j];
            if (BIAS) v += bias[n];
            if (RELU) v = fmaxf(v, 0.f);
            C[(size_t)m * N + n] = v;
        }
    }
}

// ---------------- attention logits per node: a_src, a_dst ------------------
__global__ void k_att(const float* __restrict__ xp, const float* __restrict__ asv,
                      const float* __restrict__ adv, int H)
{
    int wid  = (blockIdx.x * blockDim.x + threadIdx.x) >> 5;
    int lane = threadIdx.x & 31;
    if (wid >= NN * H) return;
    int n = wid / H, h = wid % H;
    const float* row = xp  + ((size_t)n * H + h) * 128;
    const float* as  = asv + (size_t)h * 128;
    const float* ad  = adv + (size_t)h * 128;
    float s = 0.f, d = 0.f;
#pragma unroll
    for (int c = lane; c < 128; c += 32) {
        float v = row[c];
        s += v * as[c];
        d += v * ad[c];
    }
#pragma unroll
    for (int o = 16; o; o >>= 1) {
        s += __shfl_xor_sync(~0u, s, o);
        d += __shfl_xor_sync(~0u, d, o);
    }
    if (lane == 0) { g_asrc[n * H + h] = s; g_adst[n * H + h] = d; }
}

// ---------------- CSR build (by destination; includes self loops) ----------
__global__ void k_detect64(const void* ed)
{
    if (blockIdx.x | threadIdx.x) return;
    const int* p = (const int*)ed;
    int all0 = 1;
    for (int i = 0; i < 32; i++) all0 &= (p[2 * i + 1] == 0);
    g_is64 = all0;
}
__global__ void k_deg_init()
{
    int i = blockIdx.x * blockDim.x + threadIdx.x;
    if (i < NN) g_deg[i] = 1;   // self loop
}
__global__ void k_count(const void* ed)
{
    int e = blockIdx.x * blockDim.x + threadIdx.x;
    if (e >= NE) return;
    int d = g_is64 ? (int)((const long long*)ed)[NE + e]
                   : ((const int*)ed)[NE + e];
    atomicAdd(&g_deg[d], 1);
}
__global__ void k_scan()
{
    __shared__ int sh[1024];
    __shared__ int carry;
    if (threadIdx.x == 0) carry = 0;
    __syncthreads();
    for (int base = 0; base < NN; base += 1024) {
        int i = base + threadIdx.x;
        int v = (i < NN) ? g_deg[i] : 0;
        sh[threadIdx.x] = v;
        __syncthreads();
#pragma unroll
        for (int off = 1; off < 1024; off <<= 1) {
            int t = (threadIdx.x >= off) ? sh[threadIdx.x - off] : 0;
            __syncthreads();
            sh[threadIdx.x] += t;
            __syncthreads();
        }
        int excl = carry + sh[threadIdx.x] - v;
        if (i < NN) { g_rowptr[i] = excl; g_wpos[i] = excl; }
        __syncthreads();
        if (threadIdx.x == 0) carry += sh[1023];
        __syncthreads();
    }
    if (threadIdx.x == 0) g_rowptr[NN] = carry;
}
__global__ void k_scatter(const void* ed)
{
    int e = blockIdx.x * blockDim.x + threadIdx.x;
    if (e >= NE2) return;
    int s, d;
    if (e < NE) {
        if (g_is64) { s = (int)((const long long*)ed)[e]; d = (int)((const long long*)ed)[NE + e]; }
        else        { s = ((const int*)ed)[e];            d = ((const int*)ed)[NE + e]; }
    } else {
        s = d = e - NE;
    }
    int p = atomicAdd(&g_wpos[d], 1);
    g_csrc[p] = s;
}

// ---------------- segment softmax over incoming edges (warp per dst,h) -----
__global__ void k_softmax(int H)
{
    int wid  = (blockIdx.x * blockDim.x + threadIdx.x) >> 5;
    int lane = threadIdx.x & 31;
    if (wid >= NN * H) return;
    int dst = wid / H, h = wid % H;
    int beg = g_rowptr[dst], end = g_rowptr[dst + 1];
    float ad = g_adst[dst * H + h];

    float m = -1e30f;
    for (int i = beg + lane; i < end; i += 32) {
        float e = g_asrc[g_csrc[i] * H + h] + ad;
        e = e > 0.f ? e : NEG_SLOPE * e;
        m = fmaxf(m, e);
    }
#pragma unroll
    for (int o = 16; o; o >>= 1) m = fmaxf(m, __shfl_xor_sync(~0u, m, o));

    float s = 0.f;
    for (int i = beg + lane; i < end; i += 32) {
        float e = g_asrc[g_csrc[i] * H + h] + ad;
        e = e > 0.f ? e : NEG_SLOPE * e;
        float p = __expf(e - m);
        g_alpha[(size_t)i * H + h] = p;
        s += p;
    }
#pragma unroll
    for (int o = 16; o; o >>= 1) s += __shfl_xor_sync(~0u, s, o);

    float inv = 1.f / (s + 1e-16f);
    for (int i = beg + lane; i < end; i += 32) g_alpha[(size_t)i * H + h] *= inv;
}

// ---------------- weighted aggregation (warp per dst,h; float4 lanes) ------
__global__ void k_agg(const float* __restrict__ xp, const float* __restrict__ bias,
                      float* __restrict__ out, int H)
{
    int wid  = (blockIdx.x * blockDim.x + threadIdx.x) >> 5;
    int lane = threadIdx.x & 31;
    if (wid >= NN * H) return;
    int dst = wid / H, h = wid % H;
    int beg = g_rowptr[dst], end = g_rowptr[dst + 1];

    float4 acc = make_float4(0.f, 0.f, 0.f, 0.f);
    for (int i = beg; i < end; i++) {
        int   s = g_csrc[i];
        float a = g_alpha[(size_t)i * H + h];
        float4 v = *(const float4*)(xp + ((size_t)s * H + h) * 128 + lane * 4);
        acc.x += a * v.x; acc.y += a * v.y; acc.z += a * v.z; acc.w += a * v.w;
    }
    const float* b = bias + (size_t)h * 128 + lane * 4;
    float4 r = make_float4(fmaxf(acc.x + b[0], 0.f), fmaxf(acc.y + b[1], 0.f),
                           fmaxf(acc.z + b[2], 0.f), fmaxf(acc.w + b[3], 0.f));
    *(float4*)(out + ((size_t)dst * H + h) * 128 + lane * 4) = r;
}

// ---------------- launch ----------------------------------------------------
extern "C" void kernel_launch(void* const* d_in, const int* in_sizes, int n_in,
                              void* d_out, int out_size)
{
    const float* cs    = (const float*)d_in[0];
    const float* co    = (const float*)d_in[1];
    const float* nW    = (const float*)d_in[2];
    const float* nb    = (const float*)d_in[3];
    const float* cW    = (const float*)d_in[4];
    const float* cb    = (const float*)d_in[5];
    const float* W1    = (const float*)d_in[6];
    const float* as1   = (const float*)d_in[7];
    const float* ad1   = (const float*)d_in[8];
    const float* b1    = (const float*)d_in[9];
    const float* W2    = (const float*)d_in[10];
    const float* as2   = (const float*)d_in[11];
    const float* ad2   = (const float*)d_in[12];
    const float* b2    = (const float*)d_in[13];
    const float* oW    = (const float*)d_in[14];
    const float* ob    = (const float*)d_in[15];
    const void*  edges = (const void*)d_in[16];
    float* out = (float*)d_out;

    float *p_emb0, *p_xp1, *p_emb1, *p_xp2, *p_emb2;
    cudaGetSymbolAddress((void**)&p_emb0, g_emb0);
    cudaGetSymbolAddress((void**)&p_xp1,  g_xp1);
    cudaGetSymbolAddress((void**)&p_emb1, g_emb1);
    cudaGetSymbolAddress((void**)&p_xp2,  g_xp2);
    cudaGetSymbolAddress((void**)&p_emb2, g_emb2);

    // CSR build (graph identical for both layers; flip only reorders edges)
    k_detect64<<<1, 32>>>(edges);
    k_deg_init<<<(NN + 255) / 256, 256>>>();
    k_count<<<(NE + 255) / 256, 256>>>(edges);
    k_scan<<<1, 1024>>>();
    k_scatter<<<(NE2 + 255) / 256, 256>>>(edges);

    // initial node/column embeddings
    k_embed<<<(NN * 128 + 255) / 256, 256>>>(cs, co, nW, nb, cW, cb);

    // ----- GAT layer 1 (H=8, C=128) -----
    k_gemm<false, false><<<dim3(1024 / 64, (NN + 63) / 64), 256>>>(
        p_emb0, W1, nullptr, p_xp1, NN, 1024, 128);
    k_att<<<(NN * 8) / 8, 256>>>(p_xp1, as1, ad1, 8);
    k_softmax<<<(NN * 8) / 8, 256>>>(8);
    k_agg<<<(NN * 8) / 8, 256>>>(p_xp1, b1, p_emb1, 8);

    // ----- GAT layer 2 (H=1, C=128) -----
    k_gemm<false, false><<<dim3(128 / 64, (NN + 63) / 64), 256>>>(
        p_emb1, W2, nullptr, p_xp2, NN, 128, 1024);
    k_att<<<(NN * 1 + 7) / 8, 256>>>(p_xp2, as2, ad2, 1);
    k_softmax<<<(NN * 1 + 7) / 8, 256>>>(1);
    k_agg<<<(NN * 1 + 7) / 8, 256>>>(p_xp2, b2, p_emb2, 1);

    // ----- logits = emb2[-N_COLS:] @ out_W^T + out_b -----
    k_gemm<false, true><<<dim3(128 / 64, (N_COLS + 63) / 64), 256>>>(
        p_emb2 + (size_t)N_CONS * 128, oW, ob, out, N_COLS, 128, 128);
}